// round 1
// baseline (speedup 1.0000x reference)
#include <cuda_runtime.h>

// Problem constants: B=4, N=256, OBS=40, ACT=8, HEAD=8, DIM=32, T=256
// Key simplifications (proved from reference algebra):
//   nh/hid are independent of the broadcast index i -> only column sums S_n, S_h (B,T) needed
//   final gather at tgt -> ah needed only at 4 rows

__device__ float g_E1[4 * 256 * 256];
__device__ float g_E2[4 * 256 * 256];
__device__ float g_NE[4 * 256 * 256];
__device__ float g_Sn[4 * 256];
__device__ float g_Sh[4 * 256];
__device__ float g_AH[4 * 256];

// ---------------------------------------------------------------------------
// zero the atomic accumulators
__global__ void k_init() {
    int t = blockIdx.x * blockDim.x + threadIdx.x;
    if (t < 1024) { g_Sn[t] = 0.f; g_Sh[t] = 0.f; }
}

// ---------------------------------------------------------------------------
// K1: E1 = relu(obs @ We1 + be1).  obs row (b,i) lives at x + b*257*40 + i*40.
// 4 rows per block, 256 threads = one output column each.
__global__ void k_embed1(const float* __restrict__ x, const float* __restrict__ We1,
                         const float* __restrict__ be1) {
    __shared__ float xs[4][40];
    int r0 = blockIdx.x * 4;
    int tid = threadIdx.x;
    if (tid < 160) {
        int rr = tid / 40, k = tid % 40;
        int row = r0 + rr;
        int b = row >> 8, i = row & 255;
        xs[rr][k] = x[b * 257 * 40 + i * 40 + k];
    }
    __syncthreads();
    float bias = be1[tid];
    float acc[4] = {bias, bias, bias, bias};
#pragma unroll
    for (int k = 0; k < 40; k++) {
        float w = We1[k * 256 + tid];
#pragma unroll
        for (int rr = 0; rr < 4; rr++) acc[rr] += xs[rr][k] * w;
    }
#pragma unroll
    for (int rr = 0; rr < 4; rr++)
        g_E1[(r0 + rr) * 256 + tid] = fmaxf(acc[rr], 0.f);
}

// ---------------------------------------------------------------------------
// Generic SGEMM, M x 256 x 256, BM=64 BN=32 BK=16, 256 threads, 2x4 micro-tile.
// grid = (N/32, M/64, batches); per-batch offsets in elements.
__global__ void k_gemm(const float* __restrict__ A, const float* __restrict__ B,
                       const float* __restrict__ bias, float* __restrict__ C,
                       int aOff, int bOff, int cOff, int doRelu) {
    const float* Ab = A + (size_t)blockIdx.z * aOff;
    const float* Bb = B + (size_t)blockIdx.z * bOff;
    float* Cb = C + (size_t)blockIdx.z * cOff;
    __shared__ float As[16][68];   // [k][m], padded
    __shared__ float Bs[16][32];   // [k][n]
    int tid = threadIdx.x;
    int tx = tid & 7, ty = tid >> 3;           // tx: col quad, ty: row pair
    int row0 = blockIdx.y * 64, col0 = blockIdx.x * 32;
    int arow = tid >> 2, akq = tid & 3;        // A loader: 64 rows x 4 float4
    int brow = tid >> 4, bc2 = tid & 15;       // B loader: 16 rows x 16 float2
    float acc[2][4] = {};
    for (int k0 = 0; k0 < 256; k0 += 16) {
        float4 a4 = *(const float4*)(Ab + (row0 + arow) * 256 + k0 + akq * 4);
        As[akq * 4 + 0][arow] = a4.x;
        As[akq * 4 + 1][arow] = a4.y;
        As[akq * 4 + 2][arow] = a4.z;
        As[akq * 4 + 3][arow] = a4.w;
        *(float2*)&Bs[brow][bc2 * 2] =
            *(const float2*)(Bb + (k0 + brow) * 256 + col0 + bc2 * 2);
        __syncthreads();
#pragma unroll
        for (int kk = 0; kk < 16; kk++) {
            float2 av = *(const float2*)&As[kk][ty * 2];
            float4 bv = *(const float4*)&Bs[kk][tx * 4];
            acc[0][0] += av.x * bv.x; acc[0][1] += av.x * bv.y;
            acc[0][2] += av.x * bv.z; acc[0][3] += av.x * bv.w;
            acc[1][0] += av.y * bv.x; acc[1][1] += av.y * bv.y;
            acc[1][2] += av.y * bv.z; acc[1][3] += av.y * bv.w;
        }
        __syncthreads();
    }
    float4 bi = make_float4(0.f, 0.f, 0.f, 0.f);
    if (bias) bi = *(const float4*)(bias + col0 + tx * 4);
#pragma unroll
    for (int i = 0; i < 2; i++) {
        float4 o = make_float4(acc[i][0] + bi.x, acc[i][1] + bi.y,
                               acc[i][2] + bi.z, acc[i][3] + bi.w);
        if (doRelu) {
            o.x = fmaxf(o.x, 0.f); o.y = fmaxf(o.y, 0.f);
            o.z = fmaxf(o.z, 0.f); o.w = fmaxf(o.w, 0.f);
        }
        *(float4*)(Cb + (row0 + ty * 2 + i) * 256 + col0 + tx * 4) = o;
    }
}

// ---------------------------------------------------------------------------
// K4: dual GEMM over NE (1024x256) with Wn and Wh, fused relu+bias+column-sum.
// Never materializes outputs; accumulates S_n[b,t], S_h[b,t] via atomics.
__global__ void k_dual_sum(const float* __restrict__ A, const float* __restrict__ Bn,
                           const float* __restrict__ biasn, const float* __restrict__ Bh,
                           const float* __restrict__ biash) {
    __shared__ float As[16][68];
    __shared__ float BsN[16][32];
    __shared__ float BsH[16][32];
    __shared__ float redN[32];
    __shared__ float redH[32];
    int tid = threadIdx.x;
    int tx = tid & 7, ty = tid >> 3;
    int row0 = blockIdx.y * 64, col0 = blockIdx.x * 32;
    int batch = blockIdx.y >> 2;   // 4 row tiles (of 64) per batch of 256 rows
    int arow = tid >> 2, akq = tid & 3;
    int brow = tid >> 4, bc2 = tid & 15;
    float an[2][4] = {}, ah2[2][4] = {};
    for (int k0 = 0; k0 < 256; k0 += 16) {
        float4 a4 = *(const float4*)(A + (row0 + arow) * 256 + k0 + akq * 4);
        As[akq * 4 + 0][arow] = a4.x;
        As[akq * 4 + 1][arow] = a4.y;
        As[akq * 4 + 2][arow] = a4.z;
        As[akq * 4 + 3][arow] = a4.w;
        *(float2*)&BsN[brow][bc2 * 2] =
            *(const float2*)(Bn + (k0 + brow) * 256 + col0 + bc2 * 2);
        *(float2*)&BsH[brow][bc2 * 2] =
            *(const float2*)(Bh + (k0 + brow) * 256 + col0 + bc2 * 2);
        __syncthreads();
#pragma unroll
        for (int kk = 0; kk < 16; kk++) {
            float2 av = *(const float2*)&As[kk][ty * 2];
            float4 bn4 = *(const float4*)&BsN[kk][tx * 4];
            float4 bh4 = *(const float4*)&BsH[kk][tx * 4];
            an[0][0] += av.x * bn4.x; an[0][1] += av.x * bn4.y;
            an[0][2] += av.x * bn4.z; an[0][3] += av.x * bn4.w;
            an[1][0] += av.y * bn4.x; an[1][1] += av.y * bn4.y;
            an[1][2] += av.y * bn4.z; an[1][3] += av.y * bn4.w;
            ah2[0][0] += av.x * bh4.x; ah2[0][1] += av.x * bh4.y;
            ah2[0][2] += av.x * bh4.z; ah2[0][3] += av.x * bh4.w;
            ah2[1][0] += av.y * bh4.x; ah2[1][1] += av.y * bh4.y;
            ah2[1][2] += av.y * bh4.z; ah2[1][3] += av.y * bh4.w;
        }
        __syncthreads();
    }
    if (tid < 32) { redN[tid] = 0.f; redH[tid] = 0.f; }
    __syncthreads();
    float4 bnv = *(const float4*)(biasn + col0 + tx * 4);
    float4 bhv = *(const float4*)(biash + col0 + tx * 4);
    float bna[4] = {bnv.x, bnv.y, bnv.z, bnv.w};
    float bha[4] = {bhv.x, bhv.y, bhv.z, bhv.w};
#pragma unroll
    for (int j = 0; j < 4; j++) {
        float sn = fmaxf(an[0][j] + bna[j], 0.f) + fmaxf(an[1][j] + bna[j], 0.f);
        float sh = fmaxf(ah2[0][j] + bha[j], 0.f) + fmaxf(ah2[1][j] + bha[j], 0.f);
        atomicAdd(&redN[tx * 4 + j], sn);
        atomicAdd(&redH[tx * 4 + j], sh);
    }
    __syncthreads();
    if (tid < 32) {
        atomicAdd(&g_Sn[batch * 256 + col0 + tid], redN[tid]);
        atomicAdd(&g_Sh[batch * 256 + col0 + tid], redH[tid]);
    }
}

// ---------------------------------------------------------------------------
// K5a: ah row at tgt[b]: g_AH[b,t] = relu(E2[b,tgt] . Wl[:,t] + bl[t])
__global__ void k_ah(const float* __restrict__ x, const float* __restrict__ Wl,
                     const float* __restrict__ bl) {
    __shared__ float vs[256];
    int b = blockIdx.x, t = threadIdx.x;
    int tgt = (int)x[b * 257 * 40 + 256 * 40];   // x[b, -1, 0]
    vs[t] = g_E2[b * 65536 + tgt * 256 + t];
    __syncthreads();
    float acc = bl[t];
#pragma unroll 8
    for (int k = 0; k < 256; k++) acc += vs[k] * Wl[k * 256 + t];
    g_AH[b * 256 + t] = fmaxf(acc, 0.f);
}

// ---------------------------------------------------------------------------
// K5b: per-batch: logits = ah*Sn, softmax over DIM per head (warp), head-mean
// of softmax*Sh, then 32x8 output GEMM.
__global__ void k_final(const float* __restrict__ Wa, const float* __restrict__ ba,
                        float* __restrict__ out) {
    __shared__ float od[32];
    int b = blockIdx.x, tid = threadIdx.x;
    int h = tid >> 5, d = tid & 31;
    int t = d * 8 + h;                        // reshape (DIM,HEAD) index
    float logit = g_AH[b * 256 + t] * g_Sn[b * 256 + t];
    float m = logit;
#pragma unroll
    for (int o = 16; o > 0; o >>= 1) m = fmaxf(m, __shfl_xor_sync(0xffffffffu, m, o));
    float e = expf(logit - m);
    float s = e;
#pragma unroll
    for (int o = 16; o > 0; o >>= 1) s += __shfl_xor_sync(0xffffffffu, s, o);
    float val = (e / s) * g_Sh[b * 256 + t] * 0.125f;   // mean over 8 heads
    if (tid < 32) od[tid] = 0.f;
    __syncthreads();
    atomicAdd(&od[d], val);
    __syncthreads();
    if (tid < 8) {
        float acc = ba[tid];
#pragma unroll
        for (int dd = 0; dd < 32; dd++) acc += od[dd] * Wa[dd * 8 + tid];
        out[b * 8 + tid] = acc;
    }
    (void)h;
}

// ---------------------------------------------------------------------------
extern "C" void kernel_launch(void* const* d_in, const int* in_sizes, int n_in,
                              void* d_out, int out_size) {
    const float* x   = (const float*)d_in[0];
    const float* adj = (const float*)d_in[1];
    const float* We1 = (const float*)d_in[2];
    const float* be1 = (const float*)d_in[3];
    const float* We2 = (const float*)d_in[4];
    const float* be2 = (const float*)d_in[5];
    const float* Wl  = (const float*)d_in[6];
    const float* bl  = (const float*)d_in[7];
    const float* Wn  = (const float*)d_in[8];
    const float* bn  = (const float*)d_in[9];
    const float* Wh  = (const float*)d_in[10];
    const float* bh  = (const float*)d_in[11];
    const float* Wa  = (const float*)d_in[12];
    const float* ba  = (const float*)d_in[13];
    float* out = (float*)d_out;

    float *pE1, *pE2, *pNE;
    cudaGetSymbolAddress((void**)&pE1, g_E1);
    cudaGetSymbolAddress((void**)&pE2, g_E2);
    cudaGetSymbolAddress((void**)&pNE, g_NE);

    k_init<<<4, 256>>>();
    k_embed1<<<256, 256>>>(x, We1, be1);
    // E2 = relu(E1 @ We2 + be2): M=1024
    k_gemm<<<dim3(8, 16, 1), 256>>>(pE1, We2, be2, pE2, 0, 0, 0, 1);
    // NE[b] = adj @ E2[b]: M=256, batched over z
    k_gemm<<<dim3(8, 4, 4), 256>>>(adj, pE2, nullptr, pNE, 0, 65536, 65536, 0);
    // S_n, S_h column sums of relu(NE@Wn+bn), relu(NE@Wh+bh)
    k_dual_sum<<<dim3(8, 16, 1), 256>>>(pNE, Wn, bn, Wh, bh);
    k_ah<<<4, 256>>>(x, Wl, bl);
    k_final<<<4, 256>>>(Wa, ba, out);

    (void)in_sizes; (void)n_in; (void)out_size;
}

// round 2
// speedup vs baseline: 1.3652x; 1.3652x over previous
#include <cuda_runtime.h>

// B=4, N=256, OBS=40, ACT=8, HEAD=8, DIM=32, T=256
// Algebra: nh/hid independent of broadcast index -> only column sums S_n,S_h (B,T);
// final gather at tgt -> ah needed at 4 rows only.

__device__ float g_E1[4 * 256 * 256];
__device__ float g_E2[4 * 256 * 256];
__device__ float g_NE[4 * 256 * 256];
__device__ float g_Sn[4 * 256];
__device__ float g_Sh[4 * 256];
__device__ float g_AH[4 * 256];

// ---------------------------------------------------------------------------
// K1: E1 = relu(obs @ We1 + be1); block 0 also zeroes the accumulators.
__global__ void k_embed1(const float* __restrict__ x, const float* __restrict__ We1,
                         const float* __restrict__ be1) {
    __shared__ float xs[4][40];
    int r0 = blockIdx.x * 4;
    int tid = threadIdx.x;
    if (blockIdx.x == 0) {
#pragma unroll
        for (int i = 0; i < 4; i++) {
            g_Sn[i * 256 + tid] = 0.f;
            g_Sh[i * 256 + tid] = 0.f;
            g_AH[i * 256 + tid] = 0.f;
        }
    }
    if (tid < 160) {
        int rr = tid / 40, k = tid % 40;
        int row = r0 + rr;
        int b = row >> 8, i = row & 255;
        xs[rr][k] = x[b * 257 * 40 + i * 40 + k];
    }
    __syncthreads();
    float bias = be1[tid];
    float acc[4] = {bias, bias, bias, bias};
#pragma unroll
    for (int k = 0; k < 40; k++) {
        float w = We1[k * 256 + tid];
#pragma unroll
        for (int rr = 0; rr < 4; rr++) acc[rr] += xs[rr][k] * w;
    }
#pragma unroll
    for (int rr = 0; rr < 4; rr++)
        g_E1[(r0 + rr) * 256 + tid] = fmaxf(acc[rr], 0.f);
}

// ---------------------------------------------------------------------------
// SGEMM M x 256 x 256, BM=64 BN=32 BK=16, 256 threads, 2x4 micro-tile,
// register-prefetch double-buffered smem (hides LDG latency under compute).
__global__ void k_gemm(const float* __restrict__ A, const float* __restrict__ B,
                       const float* __restrict__ bias, float* __restrict__ C,
                       int aOff, int bOff, int cOff, int doRelu) {
    const float* Ab = A + (size_t)blockIdx.z * aOff;
    const float* Bb = B + (size_t)blockIdx.z * bOff;
    float* Cb = C + (size_t)blockIdx.z * cOff;
    __shared__ float As[2][16][68];   // [stage][k][m], padded
    __shared__ float Bs[2][16][32];   // [stage][k][n]
    int tid = threadIdx.x;
    int tx = tid & 7, ty = tid >> 3;
    int row0 = blockIdx.y * 64, col0 = blockIdx.x * 32;
    int arow = tid >> 2, akq = tid & 3;
    int brow = tid >> 4, bc2 = tid & 15;
    const float* aptr = Ab + (row0 + arow) * 256 + akq * 4;
    const float* bptr = Bb + brow * 256 + col0 + bc2 * 2;

    float4 a4 = *(const float4*)aptr;
    float2 b2 = *(const float2*)bptr;
    As[0][akq * 4 + 0][arow] = a4.x;
    As[0][akq * 4 + 1][arow] = a4.y;
    As[0][akq * 4 + 2][arow] = a4.z;
    As[0][akq * 4 + 3][arow] = a4.w;
    *(float2*)&Bs[0][brow][bc2 * 2] = b2;
    __syncthreads();

    float acc[2][4] = {};
    int s = 0;
    for (int k0 = 0; k0 < 256; k0 += 16) {
        if (k0 + 16 < 256) {                 // prefetch next tile into regs
            a4 = *(const float4*)(aptr + (k0 + 16));
            b2 = *(const float2*)(bptr + (size_t)(k0 + 16) * 256);
        }
#pragma unroll
        for (int kk = 0; kk < 16; kk++) {
            float2 av = *(const float2*)&As[s][kk][ty * 2];
            float4 bv = *(const float4*)&Bs[s][kk][tx * 4];
            acc[0][0] += av.x * bv.x; acc[0][1] += av.x * bv.y;
            acc[0][2] += av.x * bv.z; acc[0][3] += av.x * bv.w;
            acc[1][0] += av.y * bv.x; acc[1][1] += av.y * bv.y;
            acc[1][2] += av.y * bv.z; acc[1][3] += av.y * bv.w;
        }
        if (k0 + 16 < 256) {
            int ns = s ^ 1;
            As[ns][akq * 4 + 0][arow] = a4.x;
            As[ns][akq * 4 + 1][arow] = a4.y;
            As[ns][akq * 4 + 2][arow] = a4.z;
            As[ns][akq * 4 + 3][arow] = a4.w;
            *(float2*)&Bs[ns][brow][bc2 * 2] = b2;
            __syncthreads();
            s = ns;
        }
    }
    float4 bi = make_float4(0.f, 0.f, 0.f, 0.f);
    if (bias) bi = *(const float4*)(bias + col0 + tx * 4);
#pragma unroll
    for (int i = 0; i < 2; i++) {
        float4 o = make_float4(acc[i][0] + bi.x, acc[i][1] + bi.y,
                               acc[i][2] + bi.z, acc[i][3] + bi.w);
        if (doRelu) {
            o.x = fmaxf(o.x, 0.f); o.y = fmaxf(o.y, 0.f);
            o.z = fmaxf(o.z, 0.f); o.w = fmaxf(o.w, 0.f);
        }
        *(float4*)(Cb + (row0 + ty * 2 + i) * 256 + col0 + tx * 4) = o;
    }
}

// ---------------------------------------------------------------------------
// Dual GEMM over NE (1024x256) with Wn & Wh, fused relu+bias+column-sum,
// double-buffered like k_gemm. Outputs only S_n, S_h via atomics.
__global__ void k_dual_sum(const float* __restrict__ A, const float* __restrict__ Bn,
                           const float* __restrict__ biasn, const float* __restrict__ Bh,
                           const float* __restrict__ biash) {
    __shared__ float As[2][16][68];
    __shared__ float BsN[2][16][32];
    __shared__ float BsH[2][16][32];
    __shared__ float redN[32];
    __shared__ float redH[32];
    int tid = threadIdx.x;
    int tx = tid & 7, ty = tid >> 3;
    int row0 = blockIdx.y * 64, col0 = blockIdx.x * 32;
    int batch = blockIdx.y >> 2;
    int arow = tid >> 2, akq = tid & 3;
    int brow = tid >> 4, bc2 = tid & 15;
    const float* aptr = A + (row0 + arow) * 256 + akq * 4;
    const float* bnptr = Bn + brow * 256 + col0 + bc2 * 2;
    const float* bhptr = Bh + brow * 256 + col0 + bc2 * 2;

    float4 a4 = *(const float4*)aptr;
    float2 b2n = *(const float2*)bnptr;
    float2 b2h = *(const float2*)bhptr;
    As[0][akq * 4 + 0][arow] = a4.x;
    As[0][akq * 4 + 1][arow] = a4.y;
    As[0][akq * 4 + 2][arow] = a4.z;
    As[0][akq * 4 + 3][arow] = a4.w;
    *(float2*)&BsN[0][brow][bc2 * 2] = b2n;
    *(float2*)&BsH[0][brow][bc2 * 2] = b2h;
    __syncthreads();

    float an[2][4] = {}, ah2[2][4] = {};
    int s = 0;
    for (int k0 = 0; k0 < 256; k0 += 16) {
        if (k0 + 16 < 256) {
            a4  = *(const float4*)(aptr + (k0 + 16));
            b2n = *(const float2*)(bnptr + (size_t)(k0 + 16) * 256);
            b2h = *(const float2*)(bhptr + (size_t)(k0 + 16) * 256);
        }
#pragma unroll
        for (int kk = 0; kk < 16; kk++) {
            float2 av = *(const float2*)&As[s][kk][ty * 2];
            float4 bn4 = *(const float4*)&BsN[s][kk][tx * 4];
            float4 bh4 = *(const float4*)&BsH[s][kk][tx * 4];
            an[0][0] += av.x * bn4.x; an[0][1] += av.x * bn4.y;
            an[0][2] += av.x * bn4.z; an[0][3] += av.x * bn4.w;
            an[1][0] += av.y * bn4.x; an[1][1] += av.y * bn4.y;
            an[1][2] += av.y * bn4.z; an[1][3] += av.y * bn4.w;
            ah2[0][0] += av.x * bh4.x; ah2[0][1] += av.x * bh4.y;
            ah2[0][2] += av.x * bh4.z; ah2[0][3] += av.x * bh4.w;
            ah2[1][0] += av.y * bh4.x; ah2[1][1] += av.y * bh4.y;
            ah2[1][2] += av.y * bh4.z; ah2[1][3] += av.y * bh4.w;
        }
        if (k0 + 16 < 256) {
            int ns = s ^ 1;
            As[ns][akq * 4 + 0][arow] = a4.x;
            As[ns][akq * 4 + 1][arow] = a4.y;
            As[ns][akq * 4 + 2][arow] = a4.z;
            As[ns][akq * 4 + 3][arow] = a4.w;
            *(float2*)&BsN[ns][brow][bc2 * 2] = b2n;
            *(float2*)&BsH[ns][brow][bc2 * 2] = b2h;
            __syncthreads();
            s = ns;
        }
    }
    if (tid < 32) { redN[tid] = 0.f; redH[tid] = 0.f; }
    __syncthreads();
    float4 bnv = *(const float4*)(biasn + col0 + tx * 4);
    float4 bhv = *(const float4*)(biash + col0 + tx * 4);
    float bna[4] = {bnv.x, bnv.y, bnv.z, bnv.w};
    float bha[4] = {bhv.x, bhv.y, bhv.z, bhv.w};
#pragma unroll
    for (int j = 0; j < 4; j++) {
        float sn = fmaxf(an[0][j] + bna[j], 0.f) + fmaxf(an[1][j] + bna[j], 0.f);
        float sh = fmaxf(ah2[0][j] + bha[j], 0.f) + fmaxf(ah2[1][j] + bha[j], 0.f);
        atomicAdd(&redN[tx * 4 + j], sn);
        atomicAdd(&redH[tx * 4 + j], sh);
    }
    __syncthreads();
    if (tid < 32) {
        atomicAdd(&g_Sn[batch * 256 + col0 + tid], redN[tid]);
        atomicAdd(&g_Sh[batch * 256 + col0 + tid], redH[tid]);
    }
}

// ---------------------------------------------------------------------------
// ah partial dot, split-K: grid = 16 (4 batches x 4 k-segments of 64).
// Accumulates E2[b,tgt,:] . Wl[:,t] into g_AH (bias+relu applied in k_final).
__global__ void k_ah(const float* __restrict__ x, const float* __restrict__ Wl) {
    __shared__ float vs[64];
    int b = blockIdx.x >> 2, kseg = blockIdx.x & 3;
    int t = threadIdx.x;
    int tgt = (int)x[b * 257 * 40 + 256 * 40];
    if (t < 64) vs[t] = g_E2[b * 65536 + tgt * 256 + kseg * 64 + t];
    __syncthreads();
    float acc = 0.f;
#pragma unroll 8
    for (int k = 0; k < 64; k++)
        acc += vs[k] * Wl[(kseg * 64 + k) * 256 + t];
    atomicAdd(&g_AH[b * 256 + t], acc);
}

// ---------------------------------------------------------------------------
// logits = relu(AH+bl)*Sn; per-head softmax over DIM; head-mean of softmax*Sh;
// 32x8 output GEMM.
__global__ void k_final(const float* __restrict__ bl, const float* __restrict__ Wa,
                        const float* __restrict__ ba, float* __restrict__ out) {
    __shared__ float od[32];
    int b = blockIdx.x, tid = threadIdx.x;
    int h = tid >> 5, d = tid & 31;
    int t = d * 8 + h;                       // (DIM,HEAD) reshape index
    float ahv = fmaxf(g_AH[b * 256 + t] + bl[t], 0.f);
    float logit = ahv * g_Sn[b * 256 + t];
    float m = logit;
#pragma unroll
    for (int o = 16; o > 0; o >>= 1) m = fmaxf(m, __shfl_xor_sync(0xffffffffu, m, o));
    float e = expf(logit - m);
    float ssum = e;
#pragma unroll
    for (int o = 16; o > 0; o >>= 1) ssum += __shfl_xor_sync(0xffffffffu, ssum, o);
    float val = (e / ssum) * g_Sh[b * 256 + t] * 0.125f;
    if (tid < 32) od[tid] = 0.f;
    __syncthreads();
    atomicAdd(&od[d], val);
    __syncthreads();
    if (tid < 8) {
        float acc = ba[tid];
#pragma unroll
        for (int dd = 0; dd < 32; dd++) acc += od[dd] * Wa[dd * 8 + tid];
        out[b * 8 + tid] = acc;
    }
}

// ---------------------------------------------------------------------------
extern "C" void kernel_launch(void* const* d_in, const int* in_sizes, int n_in,
                              void* d_out, int out_size) {
    const float* x   = (const float*)d_in[0];
    const float* adj = (const float*)d_in[1];
    const float* We1 = (const float*)d_in[2];
    const float* be1 = (const float*)d_in[3];
    const float* We2 = (const float*)d_in[4];
    const float* be2 = (const float*)d_in[5];
    const float* Wl  = (const float*)d_in[6];
    const float* bl  = (const float*)d_in[7];
    const float* Wn  = (const float*)d_in[8];
    const float* bn  = (const float*)d_in[9];
    const float* Wh  = (const float*)d_in[10];
    const float* bh  = (const float*)d_in[11];
    const float* Wa  = (const float*)d_in[12];
    const float* ba  = (const float*)d_in[13];
    float* out = (float*)d_out;

    float *pE1, *pE2, *pNE;
    cudaGetSymbolAddress((void**)&pE1, g_E1);
    cudaGetSymbolAddress((void**)&pE2, g_E2);
    cudaGetSymbolAddress((void**)&pNE, g_NE);

    k_embed1<<<256, 256>>>(x, We1, be1);
    k_gemm<<<dim3(8, 16, 1), 256>>>(pE1, We2, be2, pE2, 0, 0, 0, 1);       // E2
    k_gemm<<<dim3(8, 4, 4), 256>>>(adj, pE2, nullptr, pNE, 0, 65536, 65536, 0); // NE
    k_dual_sum<<<dim3(8, 16, 1), 256>>>(pNE, Wn, bn, Wh, bh);              // S_n,S_h
    k_ah<<<16, 256>>>(x, Wl);
    k_final<<<4, 256>>>(bl, Wa, ba, out);

    (void)in_sizes; (void)n_in; (void)out_size;
}

// round 3
// speedup vs baseline: 1.3856x; 1.0150x over previous
#include <cuda_runtime.h>

// B=4, N=256, OBS=40, ACT=8, HEAD=8, DIM=32, T=256
// Algebra: nh/hid independent of broadcast index -> only column sums S_n,S_h (B,T);
// final gather at tgt -> ah needed at 4 rows only.
// Split-K=2 (atomic-free): producers write two partial buffers; consumers add at load.

__device__ float g_E1[1024 * 256];
__device__ float g_E2[2 * 1024 * 256];   // [ksplit][row][col] partials of E1@We2
__device__ float g_NE[2 * 1024 * 256];   // [ksplit][b*256+i][col] partials of adj@relu_E2
__device__ float g_Sn[1024];
__device__ float g_Sh[1024];
__device__ float g_AH[1024];

#define E2_HALF (1024 * 256)

// ---------------------------------------------------------------------------
// K1: E1 = relu(obs @ We1 + be1); block 0 also zeroes the accumulators.
__global__ void k_embed1(const float* __restrict__ x, const float* __restrict__ We1,
                         const float* __restrict__ be1) {
    __shared__ float xs[4][40];
    int r0 = blockIdx.x * 4;
    int tid = threadIdx.x;
    if (blockIdx.x == 0) {
#pragma unroll
        for (int i = 0; i < 4; i++) {
            g_Sn[i * 256 + tid] = 0.f;
            g_Sh[i * 256 + tid] = 0.f;
            g_AH[i * 256 + tid] = 0.f;
        }
    }
    if (tid < 160) {
        int rr = tid / 40, k = tid % 40;
        int row = r0 + rr;
        int b = row >> 8, i = row & 255;
        xs[rr][k] = x[b * 257 * 40 + i * 40 + k];
    }
    __syncthreads();
    float bias = be1[tid];
    float acc[4] = {bias, bias, bias, bias};
#pragma unroll
    for (int k = 0; k < 40; k++) {
        float w = We1[k * 256 + tid];
#pragma unroll
        for (int rr = 0; rr < 4; rr++) acc[rr] += xs[rr][k] * w;
    }
#pragma unroll
    for (int rr = 0; rr < 4; rr++)
        g_E1[(r0 + rr) * 256 + tid] = fmaxf(acc[rr], 0.f);
}

// ---------------------------------------------------------------------------
// K2: E2 partial = E1 @ We2 over K-half blockIdx.z. No bias/relu (consumer adds).
// BM=64 BN=32 BK=16, 256 thr, 2x4 microtile, double-buffered. grid (8,16,2).
__global__ void __launch_bounds__(256) k_gemmE2(const float* __restrict__ E1,
                                                const float* __restrict__ We2) {
    __shared__ float As[2][16][68];
    __shared__ float Bs[2][16][32];
    int tid = threadIdx.x;
    int tx = tid & 7, ty = tid >> 3;
    int row0 = blockIdx.y * 64, col0 = blockIdx.x * 32, kb = blockIdx.z * 128;
    int arow = tid >> 2, akq = tid & 3;
    int brow = tid >> 4, bc2 = tid & 15;
    const float* aptr = E1 + (row0 + arow) * 256 + kb + akq * 4;
    const float* bptr = We2 + (kb + brow) * 256 + col0 + bc2 * 2;

    float4 a4 = *(const float4*)aptr;
    float2 b2 = *(const float2*)bptr;
    As[0][akq * 4 + 0][arow] = a4.x; As[0][akq * 4 + 1][arow] = a4.y;
    As[0][akq * 4 + 2][arow] = a4.z; As[0][akq * 4 + 3][arow] = a4.w;
    *(float2*)&Bs[0][brow][bc2 * 2] = b2;
    __syncthreads();

    float acc[2][4] = {};
    int s = 0;
    for (int k0 = 0; k0 < 128; k0 += 16) {
        if (k0 + 16 < 128) {
            a4 = *(const float4*)(aptr + k0 + 16);
            b2 = *(const float2*)(bptr + (size_t)(k0 + 16) * 256);
        }
#pragma unroll
        for (int kk = 0; kk < 16; kk++) {
            float2 av = *(const float2*)&As[s][kk][ty * 2];
            float4 bv = *(const float4*)&Bs[s][kk][tx * 4];
            acc[0][0] += av.x * bv.x; acc[0][1] += av.x * bv.y;
            acc[0][2] += av.x * bv.z; acc[0][3] += av.x * bv.w;
            acc[1][0] += av.y * bv.x; acc[1][1] += av.y * bv.y;
            acc[1][2] += av.y * bv.z; acc[1][3] += av.y * bv.w;
        }
        if (k0 + 16 < 128) {
            int ns = s ^ 1;
            As[ns][akq * 4 + 0][arow] = a4.x; As[ns][akq * 4 + 1][arow] = a4.y;
            As[ns][akq * 4 + 2][arow] = a4.z; As[ns][akq * 4 + 3][arow] = a4.w;
            *(float2*)&Bs[ns][brow][bc2 * 2] = b2;
            __syncthreads();
            s = ns;
        }
    }
    float* outp = g_E2 + (size_t)blockIdx.z * E2_HALF;
#pragma unroll
    for (int i = 0; i < 2; i++)
        *(float4*)(outp + (row0 + ty * 2 + i) * 256 + col0 + tx * 4) =
            make_float4(acc[i][0], acc[i][1], acc[i][2], acc[i][3]);
}

// ---------------------------------------------------------------------------
// K3: NE partial = adj[:, kb:kb+128] @ relu(E2a+E2b+be2)[rows kb:kb+128].
// z = b*2 + ks. grid (8,4,8).
__global__ void __launch_bounds__(256) k_gemmNE(const float* __restrict__ adj,
                                                const float* __restrict__ be2) {
    __shared__ float As[2][16][68];
    __shared__ float Bs[2][16][32];
    int tid = threadIdx.x;
    int tx = tid & 7, ty = tid >> 3;
    int b = blockIdx.z >> 1, ks = blockIdx.z & 1, kb = ks * 128;
    int row0 = blockIdx.y * 64, col0 = blockIdx.x * 32;
    int arow = tid >> 2, akq = tid & 3;
    int brow = tid >> 4, bc2 = tid & 15;
    const float* aptr = adj + (row0 + arow) * 256 + kb + akq * 4;
    const float* pa = g_E2 + (size_t)(b * 256 + kb + brow) * 256 + col0 + bc2 * 2;
    const float* pb = pa + E2_HALF;
    float2 bias = *(const float2*)(be2 + col0 + bc2 * 2);

    float4 a4 = *(const float4*)aptr;
    float2 ea = *(const float2*)pa;
    float2 eb = *(const float2*)pb;
    As[0][akq * 4 + 0][arow] = a4.x; As[0][akq * 4 + 1][arow] = a4.y;
    As[0][akq * 4 + 2][arow] = a4.z; As[0][akq * 4 + 3][arow] = a4.w;
    Bs[0][brow][bc2 * 2 + 0] = fmaxf(ea.x + eb.x + bias.x, 0.f);
    Bs[0][brow][bc2 * 2 + 1] = fmaxf(ea.y + eb.y + bias.y, 0.f);
    __syncthreads();

    float acc[2][4] = {};
    int s = 0;
    for (int k0 = 0; k0 < 128; k0 += 16) {
        if (k0 + 16 < 128) {
            a4 = *(const float4*)(aptr + k0 + 16);
            ea = *(const float2*)(pa + (size_t)(k0 + 16) * 256);
            eb = *(const float2*)(pb + (size_t)(k0 + 16) * 256);
        }
#pragma unroll
        for (int kk = 0; kk < 16; kk++) {
            float2 av = *(const float2*)&As[s][kk][ty * 2];
            float4 bv = *(const float4*)&Bs[s][kk][tx * 4];
            acc[0][0] += av.x * bv.x; acc[0][1] += av.x * bv.y;
            acc[0][2] += av.x * bv.z; acc[0][3] += av.x * bv.w;
            acc[1][0] += av.y * bv.x; acc[1][1] += av.y * bv.y;
            acc[1][2] += av.y * bv.z; acc[1][3] += av.y * bv.w;
        }
        if (k0 + 16 < 128) {
            int ns = s ^ 1;
            As[ns][akq * 4 + 0][arow] = a4.x; As[ns][akq * 4 + 1][arow] = a4.y;
            As[ns][akq * 4 + 2][arow] = a4.z; As[ns][akq * 4 + 3][arow] = a4.w;
            Bs[ns][brow][bc2 * 2 + 0] = fmaxf(ea.x + eb.x + bias.x, 0.f);
            Bs[ns][brow][bc2 * 2 + 1] = fmaxf(ea.y + eb.y + bias.y, 0.f);
            __syncthreads();
            s = ns;
        }
    }
    float* outp = g_NE + (size_t)ks * E2_HALF + (size_t)(b * 256) * 256;
#pragma unroll
    for (int i = 0; i < 2; i++)
        *(float4*)(outp + (row0 + ty * 2 + i) * 256 + col0 + tx * 4) =
            make_float4(acc[i][0], acc[i][1], acc[i][2], acc[i][3]);
}

// ---------------------------------------------------------------------------
// K4: column sums of relu((NEa+NEb) @ W + bias); z=0 -> Wn/bn/Sn, z=1 -> Wh/bh/Sh.
// Full K=256 (relu forbids split-K). grid (8,16,2).
__global__ void __launch_bounds__(256) k_colsum(const float* __restrict__ Wn,
                                                const float* __restrict__ bn,
                                                const float* __restrict__ Wh,
                                                const float* __restrict__ bh) {
    __shared__ float As[2][16][68];
    __shared__ float Bs[2][16][32];
    __shared__ float red[32];
    const float* W = blockIdx.z ? Wh : Wn;
    const float* bias = blockIdx.z ? bh : bn;
    float* S = blockIdx.z ? g_Sh : g_Sn;
    int tid = threadIdx.x;
    int tx = tid & 7, ty = tid >> 3;
    int row0 = blockIdx.y * 64, col0 = blockIdx.x * 32;
    int batch = blockIdx.y >> 2;
    int arow = tid >> 2, akq = tid & 3;
    int brow = tid >> 4, bc2 = tid & 15;
    const float* pa = g_NE + (size_t)(row0 + arow) * 256 + akq * 4;
    const float* pb = pa + E2_HALF;
    const float* bptr = W + brow * 256 + col0 + bc2 * 2;

    float4 a4 = *(const float4*)pa;
    float4 a4b = *(const float4*)pb;
    float2 b2 = *(const float2*)bptr;
    As[0][akq * 4 + 0][arow] = a4.x + a4b.x; As[0][akq * 4 + 1][arow] = a4.y + a4b.y;
    As[0][akq * 4 + 2][arow] = a4.z + a4b.z; As[0][akq * 4 + 3][arow] = a4.w + a4b.w;
    *(float2*)&Bs[0][brow][bc2 * 2] = b2;
    __syncthreads();

    float acc[2][4] = {};
    int s = 0;
    for (int k0 = 0; k0 < 256; k0 += 16) {
        if (k0 + 16 < 256) {
            a4  = *(const float4*)(pa + k0 + 16);
            a4b = *(const float4*)(pb + k0 + 16);
            b2  = *(const float2*)(bptr + (size_t)(k0 + 16) * 256);
        }
#pragma unroll
        for (int kk = 0; kk < 16; kk++) {
            float2 av = *(const float2*)&As[s][kk][ty * 2];
            float4 bv = *(const float4*)&Bs[s][kk][tx * 4];
            acc[0][0] += av.x * bv.x; acc[0][1] += av.x * bv.y;
            acc[0][2] += av.x * bv.z; acc[0][3] += av.x * bv.w;
            acc[1][0] += av.y * bv.x; acc[1][1] += av.y * bv.y;
            acc[1][2] += av.y * bv.z; acc[1][3] += av.y * bv.w;
        }
        if (k0 + 16 < 256) {
            int ns = s ^ 1;
            As[ns][akq * 4 + 0][arow] = a4.x + a4b.x; As[ns][akq * 4 + 1][arow] = a4.y + a4b.y;
            As[ns][akq * 4 + 2][arow] = a4.z + a4b.z; As[ns][akq * 4 + 3][arow] = a4.w + a4b.w;
            *(float2*)&Bs[ns][brow][bc2 * 2] = b2;
            __syncthreads();
            s = ns;
        }
    }
    if (tid < 32) red[tid] = 0.f;
    __syncthreads();
    float4 bi = *(const float4*)(bias + col0 + tx * 4);
    float ba4[4] = {bi.x, bi.y, bi.z, bi.w};
#pragma unroll
    for (int j = 0; j < 4; j++) {
        float sv = fmaxf(acc[0][j] + ba4[j], 0.f) + fmaxf(acc[1][j] + ba4[j], 0.f);
        // reduce over the 4 ty-subrows within the warp (lane bits 3,4)
        sv += __shfl_xor_sync(0xffffffffu, sv, 8);
        sv += __shfl_xor_sync(0xffffffffu, sv, 16);
        if ((tid & 31) < 8) atomicAdd(&red[tx * 4 + j], sv);
    }
    __syncthreads();
    if (tid < 32) atomicAdd(&S[batch * 256 + col0 + tid], red[tid]);
}

// ---------------------------------------------------------------------------
// ah split-K partials: grid 16 (4 batches x 4 k-segments of 64).
// vs = relu(E2a+E2b+be2) at row tgt; accumulates into g_AH.
__global__ void k_ah(const float* __restrict__ x, const float* __restrict__ Wl,
                     const float* __restrict__ be2) {
    __shared__ float vs[64];
    int b = blockIdx.x >> 2, kseg = blockIdx.x & 3;
    int t = threadIdx.x;
    int tgt = (int)x[b * 257 * 40 + 256 * 40];
    if (t < 64) {
        int col = kseg * 64 + t;
        size_t idx = (size_t)(b * 256 + tgt) * 256 + col;
        vs[t] = fmaxf(g_E2[idx] + g_E2[E2_HALF + idx] + be2[col], 0.f);
    }
    __syncthreads();
    float acc = 0.f;
#pragma unroll 8
    for (int k = 0; k < 64; k++)
        acc += vs[k] * Wl[(kseg * 64 + k) * 256 + t];
    atomicAdd(&g_AH[b * 256 + t], acc);
}

// ---------------------------------------------------------------------------
// logits = relu(AH+bl)*Sn; per-head softmax over DIM; head-mean of softmax*Sh;
// 32x8 output GEMM.
__global__ void k_final(const float* __restrict__ bl, const float* __restrict__ Wa,
                        const float* __restrict__ ba, float* __restrict__ out) {
    __shared__ float od[32];
    int b = blockIdx.x, tid = threadIdx.x;
    int h = tid >> 5, d = tid & 31;
    int t = d * 8 + h;                       // (DIM,HEAD) reshape index
    float ahv = fmaxf(g_AH[b * 256 + t] + bl[t], 0.f);
    float logit = ahv * g_Sn[b * 256 + t];
    float m = logit;
#pragma unroll
    for (int o = 16; o > 0; o >>= 1) m = fmaxf(m, __shfl_xor_sync(0xffffffffu, m, o));
    float e = expf(logit - m);
    float ssum = e;
#pragma unroll
    for (int o = 16; o > 0; o >>= 1) ssum += __shfl_xor_sync(0xffffffffu, ssum, o);
    float val = (e / ssum) * g_Sh[b * 256 + t] * 0.125f;
    if (tid < 32) od[tid] = 0.f;
    __syncthreads();
    atomicAdd(&od[d], val);
    __syncthreads();
    if (tid < 8) {
        float acc = ba[tid];
#pragma unroll
        for (int dd = 0; dd < 32; dd++) acc += od[dd] * Wa[dd * 8 + tid];
        out[b * 8 + tid] = acc;
    }
    (void)h;
}

// ---------------------------------------------------------------------------
extern "C" void kernel_launch(void* const* d_in, const int* in_sizes, int n_in,
                              void* d_out, int out_size) {
    const float* x   = (const float*)d_in[0];
    const float* adj = (const float*)d_in[1];
    const float* We1 = (const float*)d_in[2];
    const float* be1 = (const float*)d_in[3];
    const float* We2 = (const float*)d_in[4];
    const float* be2 = (const float*)d_in[5];
    const float* Wl  = (const float*)d_in[6];
    const float* bl  = (const float*)d_in[7];
    const float* Wn  = (const float*)d_in[8];
    const float* bn  = (const float*)d_in[9];
    const float* Wh  = (const float*)d_in[10];
    const float* bh  = (const float*)d_in[11];
    const float* Wa  = (const float*)d_in[12];
    const float* ba  = (const float*)d_in[13];
    float* out = (float*)d_out;

    float* pE1;
    cudaGetSymbolAddress((void**)&pE1, g_E1);

    k_embed1<<<256, 256>>>(x, We1, be1);
    k_gemmE2<<<dim3(8, 16, 2), 256>>>(pE1, We2);      // E2 partials (split-K)
    k_gemmNE<<<dim3(8, 4, 8), 256>>>(adj, be2);       // NE partials (split-K, fused relu)
    k_colsum<<<dim3(8, 16, 2), 256>>>(Wn, bn, Wh, bh);// S_n, S_h
    k_ah<<<16, 256>>>(x, Wl, be2);
    k_final<<<4, 256>>>(bl, Wa, ba, out);

    (void)in_sizes; (void)n_in; (void)out_size;
}